// round 4
// baseline (speedup 1.0000x reference)
#include <cuda_runtime.h>
#include <cuda_bf16.h>
#include <math.h>
#include <stdint.h>

// ---------------- problem constants ----------------------------------------
#define T_TOK 4096
#define D_DIM 1024
#define E_NUM 8
#define W_DIM 1024
#define SLOTS 8192          // T*2 (top-2)
#define K2    2048          // stored K: [hi | lo]
#define BK    32
#define NCH   96            // effective K = 3072 (3-term bf16x3), chunks of 32
#define SAS   40            // smem row stride in bf16 (80B) -> conflict-free LDSM
#define STAGES 4
#define AST   10240         // bytes per stage per operand: 128 * 40 * 2

// ---------------- device scratch --------------------------------------------
__device__ int   g_count[E_NUM];
__device__ int   g_fill [E_NUM];
__device__ int   g_off  [E_NUM + 1];
__device__ int   g_sel  [T_TOK * 2];
__device__ float g_selw [T_TOK * 2];
__device__ int   g_tok  [SLOTS];
__device__ float g_wt   [SLOTS];
__device__ __nv_bfloat16 g_xcat [(size_t)T_TOK * K2];          // 16.8 MB
__device__ __nv_bfloat16 g_w1cat[(size_t)E_NUM * W_DIM * K2];  // 33.5 MB [e][n][k]
__device__ __nv_bfloat16 g_w2cat[(size_t)E_NUM * D_DIM * K2];  // 33.5 MB [e][d][k]
__device__ __nv_bfloat16 g_acat [(size_t)SLOTS * K2];          // 33.5 MB [slot][k]

// ---------------- PTX helpers ------------------------------------------------
__device__ __forceinline__ uint32_t smem_u32(const void* p) {
    uint32_t a;
    asm("{ .reg .u64 t; cvta.to.shared.u64 t, %1; cvt.u32.u64 %0, t; }" : "=r"(a) : "l"(p));
    return a;
}
#define CP16(sm, gp) \
    asm volatile("cp.async.cg.shared.global [%0], [%1], 16;" :: "r"(sm), "l"(gp))
#define CPCOMMIT() asm volatile("cp.async.commit_group;")
template <int N> __device__ __forceinline__ void cpwait() {
    asm volatile("cp.async.wait_group %0;" :: "n"(N));
}
__device__ __forceinline__ void ldsm_x4(uint32_t* r, uint32_t addr) {
    asm volatile("ldmatrix.sync.aligned.m8n8.x4.shared.b16 {%0,%1,%2,%3}, [%4];"
        : "=r"(r[0]), "=r"(r[1]), "=r"(r[2]), "=r"(r[3]) : "r"(addr));
}
__device__ __forceinline__ void mma16816(float* d, const uint32_t* a, uint32_t b0, uint32_t b1) {
    asm volatile(
        "mma.sync.aligned.m16n8k16.row.col.f32.bf16.bf16.f32 "
        "{%0,%1,%2,%3}, {%4,%5,%6,%7}, {%8,%9}, {%0,%1,%2,%3};"
        : "+f"(d[0]), "+f"(d[1]), "+f"(d[2]), "+f"(d[3])
        : "r"(a[0]), "r"(a[1]), "r"(a[2]), "r"(a[3]), "r"(b0), "r"(b1));
}

// chunk -> stored-K offset.  A pattern [hi|hi|lo], B pattern [hi|lo|hi]
__device__ __forceinline__ int kbA(int c) {
    return (c < 32) ? c * 32 : (c < 64 ? (c - 32) * 32 : c * 32 - 1024);
}
__device__ __forceinline__ int kbB(int c) {
    return (c < 64) ? c * 32 : (c - 64) * 32;
}

// ---------------- small kernels ---------------------------------------------
__global__ void zero_kernel(float* __restrict__ out) {
    int i = blockIdx.x * blockDim.x + threadIdx.x;
    if (i < T_TOK * D_DIM) out[i] = 0.0f;
    if (i < E_NUM) { g_count[i] = 0; g_fill[i] = 0; }
}

__global__ void router_kernel(const float* __restrict__ x, const float* __restrict__ rw) {
    int warp = (blockIdx.x * blockDim.x + threadIdx.x) >> 5;
    int lane = threadIdx.x & 31;
    if (warp >= T_TOK) return;
    const float* xr = x + (size_t)warp * D_DIM;
    float p[E_NUM];
#pragma unroll
    for (int e = 0; e < E_NUM; e++) p[e] = 0.0f;
    for (int d = lane; d < D_DIM; d += 32) {
        float xv = xr[d];
#pragma unroll
        for (int e = 0; e < E_NUM; e++) p[e] += xv * rw[e * D_DIM + d];
    }
#pragma unroll
    for (int e = 0; e < E_NUM; e++)
#pragma unroll
        for (int o = 16; o; o >>= 1) p[e] += __shfl_xor_sync(0xffffffffu, p[e], o);
    if (lane == 0) {
        int i1 = 0; float v1 = p[0];
#pragma unroll
        for (int e = 1; e < E_NUM; e++) if (p[e] > v1) { v1 = p[e]; i1 = e; }
        int i2 = -1; float v2 = -3.0e38f;
#pragma unroll
        for (int e = 0; e < E_NUM; e++) if (e != i1 && p[e] > v2) { v2 = p[e]; i2 = e; }
        float p1 = 1.0f / (1.0f + expf(-v1));
        float p2 = 1.0f / (1.0f + expf(-v2));
        float s = p1 + p2 + 1e-20f;
        g_sel [warp * 2 + 0] = i1;  g_sel [warp * 2 + 1] = i2;
        g_selw[warp * 2 + 0] = p1 / s;
        g_selw[warp * 2 + 1] = p2 / s;
        atomicAdd(&g_count[i1], 1);
        atomicAdd(&g_count[i2], 1);
    }
}

__global__ void offsets_kernel() {
    if (threadIdx.x == 0 && blockIdx.x == 0) {
        int s = 0;
#pragma unroll
        for (int e = 0; e < E_NUM; e++) { g_off[e] = s; s += g_count[e]; }
        g_off[E_NUM] = s;
    }
}

__global__ void fill_kernel() {
    int t = blockIdx.x * blockDim.x + threadIdx.x;
    if (t >= T_TOK) return;
#pragma unroll
    for (int k = 0; k < 2; k++) {
        int e = g_sel[t * 2 + k];
        int pos = g_off[e] + atomicAdd(&g_fill[e], 1);
        g_tok[pos] = t;
        g_wt [pos] = g_selw[t * 2 + k];
    }
}

// x -> [hi | lo] bf16, row-major [T][2048]
__global__ void convert_x(const float* __restrict__ x) {
    int i = blockIdx.x * blockDim.x + threadIdx.x;
    if (i >= T_TOK * D_DIM) return;
    int t = i >> 10, d = i & 1023;
    float v = x[i];
    __nv_bfloat16 hi = __float2bfloat16(v);
    __nv_bfloat16 lo = __float2bfloat16(v - __bfloat162float(hi));
    size_t b = (size_t)t * K2;
    g_xcat[b + d] = hi; g_xcat[b + 1024 + d] = lo;
}

// Per-expert 1024x1024 transpose + split -> [e][n][hi(1024)|lo(1024)]
__global__ void convert_w(const float* __restrict__ src, int sel) {
    __shared__ float tile[32][33];
    int e = blockIdx.z;
    int r0 = blockIdx.y * 32, c0 = blockIdx.x * 32;
    int src_ld  = sel ? 1024 : 8192;
    int row_off = sel ? e * 1024 : 0;
    int col_off = sel ? 0 : e * 1024;
    const float* s = src + (size_t)(row_off + r0) * src_ld + col_off + c0;
#pragma unroll
    for (int i = threadIdx.y; i < 32; i += 8)
        tile[i][threadIdx.x] = s[(size_t)i * src_ld + threadIdx.x];
    __syncthreads();
    __nv_bfloat16* d = (sel ? g_w2cat : g_w1cat) + (size_t)e * 1024 * K2;
#pragma unroll
    for (int i = threadIdx.y; i < 32; i += 8) {
        int c = c0 + i;               // dst row (N index)
        int r = r0 + threadIdx.x;     // dst col (K index)
        float v = tile[threadIdx.x][i];
        __nv_bfloat16 hi = __float2bfloat16(v);
        __nv_bfloat16 lo = __float2bfloat16(v - __bfloat162float(hi));
        size_t bi = (size_t)c * K2 + r;
        d[bi] = hi; d[bi + 1024] = lo;
    }
}

// ---------------- grouped GEMM (HMMA, cp.async 4-stage, ldmatrix) -----------
// MODE 0: up-proj  (A = g_xcat by token, B = g_w1cat, epi -> g_acat split)
// MODE 1: down-proj(A = g_acat by slot,  B = g_w2cat, epi -> atomicAdd out)
template <int MODE>
__global__ void __launch_bounds__(256, 2) moe_gemm(float* __restrict__ out) {
    extern __shared__ char sm[];
    int*   tok_s = (int*)  (sm + 2 * STAGES * AST);
    float* wt_s  = (float*)(tok_s + 128);
    uint32_t AsmU = smem_u32(sm);
    uint32_t BsmU = AsmU + STAGES * AST;

    int e = blockIdx.z;
    int cnt = g_count[e];
    int m0 = blockIdx.y * 128;
    if (m0 >= cnt) return;
    int base = g_off[e];
    int n0 = blockIdx.x * 128;

    int tid = threadIdx.x, lane = tid & 31, wid = tid >> 5;
    int wm = wid & 1, wn = wid >> 1;        // warps 2x4 -> 64x32 tile per warp
    int g = lane >> 2, tig = lane & 3;

    if (tid < 128) {
        int slot = base + m0 + tid; if (slot >= SLOTS) slot = SLOTS - 1;
        tok_s[tid] = g_tok[slot];
        wt_s [tid] = g_wt[slot];
    }
    __syncthreads();

    const __nv_bfloat16* Bexp = (MODE ? g_w2cat : g_w1cat) + (size_t)e * 1024 * K2;

    // per-thread cp.async assignment: row = tid>>1 (0..127), two 16B segs
    int lrow = tid >> 1;
    int lseg = (tid & 1) * 16;                 // elem offset: 0 or 16 (of 32)
    const __nv_bfloat16* Agp;
    if (MODE == 0) {
        Agp = g_xcat + (size_t)tok_s[lrow] * K2;
    } else {
        int sl = base + m0 + lrow; if (sl >= SLOTS) sl = SLOTS - 1;
        Agp = g_acat + (size_t)sl * K2;
    }
    const __nv_bfloat16* Bgp = Bexp + (size_t)(n0 + lrow) * K2;
    uint32_t Asm_t = AsmU + lrow * (SAS * 2) + lseg * 2;
    uint32_t Bsm_t = BsmU + lrow * (SAS * 2) + lseg * 2;

    // prologue: stages 0..STAGES-2
#pragma unroll
    for (int s = 0; s < STAGES - 1; s++) {
        int ka = kbA(s), kb = kbB(s);
        CP16(Asm_t + s * AST,      Agp + ka + lseg);
        CP16(Asm_t + s * AST + 16, Agp + ka + lseg + 8);
        CP16(Bsm_t + s * AST,      Bgp + kb + lseg);
        CP16(Bsm_t + s * AST + 16, Bgp + kb + lseg + 8);
        CPCOMMIT();
    }

    float acc[4][4][4];
#pragma unroll
    for (int i = 0; i < 4; i++)
#pragma unroll
        for (int j = 0; j < 4; j++)
#pragma unroll
            for (int q = 0; q < 4; q++) acc[i][j][q] = 0.0f;

    // ldmatrix per-thread row/col offsets (same formula for A and B tiles)
    uint32_t ro = (lane & 7) + ((lane >> 3) & 1) * 8;
    uint32_t co = ((lane >> 4) & 1) * 8;

#pragma unroll 1
    for (int c = 0; c < NCH; c++) {
        cpwait<STAGES - 2>();       // group c complete
        __syncthreads();            // data visible; stage (c-1)%S free

        int ci = c + STAGES - 1;
        if (ci < NCH) {
            int st = ci & (STAGES - 1);
            int ka = kbA(ci), kb = kbB(ci);
            CP16(Asm_t + st * AST,      Agp + ka + lseg);
            CP16(Asm_t + st * AST + 16, Agp + ka + lseg + 8);
            CP16(Bsm_t + st * AST,      Bgp + kb + lseg);
            CP16(Bsm_t + st * AST + 16, Bgp + kb + lseg + 8);
        }
        CPCOMMIT();

        int st = c & (STAGES - 1);
        uint32_t Ac = AsmU + st * AST;
        uint32_t Bc = BsmU + st * AST;
#pragma unroll
        for (int ks = 0; ks < 2; ks++) {
            uint32_t kc = ks * 16 + co;
            uint32_t af[4][4], bfr[2][4];
#pragma unroll
            for (int mt = 0; mt < 4; mt++)
                ldsm_x4(af[mt], Ac + (wm * 64 + mt * 16 + ro) * (SAS * 2) + kc * 2);
#pragma unroll
            for (int p = 0; p < 2; p++)
                ldsm_x4(bfr[p], Bc + (wn * 32 + p * 16 + ro) * (SAS * 2) + kc * 2);
#pragma unroll
            for (int mt = 0; mt < 4; mt++)
#pragma unroll
                for (int nt = 0; nt < 4; nt++)
                    mma16816(acc[mt][nt], af[mt], bfr[nt >> 1][nt & 1], bfr[nt >> 1][(nt & 1) + 2]);
        }
    }

    // ---------------- epilogue ----------------
#pragma unroll
    for (int mt = 0; mt < 4; mt++) {
#pragma unroll
        for (int half = 0; half < 2; half++) {
            int ml = wm * 64 + mt * 16 + g + half * 8;   // local row 0..127
            int m = m0 + ml;
            if (m >= cnt) continue;
            if (MODE == 0) {
                int slot = base + m;
                float wt = wt_s[ml];
                __nv_bfloat16* dst = g_acat + (size_t)slot * K2;
#pragma unroll
                for (int nt = 0; nt < 4; nt++) {
                    int n = n0 + wn * 32 + nt * 8 + tig * 2;
                    float h0 = acc[mt][nt][half * 2 + 0];
                    float h1 = acc[mt][nt][half * 2 + 1];
                    float a0 = (h0 > 0.0f) ? wt * h0 * h0 : 0.0f;
                    float a1 = (h1 > 0.0f) ? wt * h1 * h1 : 0.0f;
                    __nv_bfloat16 hi0 = __float2bfloat16(a0);
                    __nv_bfloat16 hi1 = __float2bfloat16(a1);
                    __nv_bfloat16 lo0 = __float2bfloat16(a0 - __bfloat162float(hi0));
                    __nv_bfloat16 lo1 = __float2bfloat16(a1 - __bfloat162float(hi1));
                    __nv_bfloat162 hh; hh.x = hi0; hh.y = hi1;
                    __nv_bfloat162 ll; ll.x = lo0; ll.y = lo1;
                    *(__nv_bfloat162*)(dst + n)        = hh;
                    *(__nv_bfloat162*)(dst + 1024 + n) = ll;
                }
            } else {
                int tok = tok_s[ml];
                float* orow = out + (size_t)tok * D_DIM;
#pragma unroll
                for (int nt = 0; nt < 4; nt++) {
                    int n = n0 + wn * 32 + nt * 8 + tig * 2;
                    atomicAdd(&orow[n],     acc[mt][nt][half * 2 + 0]);
                    atomicAdd(&orow[n + 1], acc[mt][nt][half * 2 + 1]);
                }
            }
        }
    }
}

// ---------------- launch ------------------------------------------------------
extern "C" void kernel_launch(void* const* d_in, const int* in_sizes, int n_in,
                              void* d_out, int out_size) {
    const float* x  = (const float*)d_in[0];   // [2,2048,1024]
    const float* rw = (const float*)d_in[1];   // [8,1024]
    const float* w1 = (const float*)d_in[2];   // [1024, 8192]
    const float* w2 = (const float*)d_in[3];   // [8192, 1024]
    float* out = (float*)d_out;

    zero_kernel<<<(T_TOK * D_DIM + 255) / 256, 256>>>(out);
    convert_x<<<(T_TOK * D_DIM + 255) / 256, 256>>>(x);

    dim3 tg(32, 32, E_NUM), tb(32, 8);
    convert_w<<<tg, tb>>>(w1, 0);
    convert_w<<<tg, tb>>>(w2, 1);

    router_kernel<<<(T_TOK * 32 + 255) / 256, 256>>>(x, rw);
    offsets_kernel<<<1, 32>>>();
    fill_kernel<<<(T_TOK + 255) / 256, 256>>>();

    int shmem = 2 * STAGES * AST + 1024;  // 82944 B
    cudaFuncSetAttribute(moe_gemm<0>, cudaFuncAttributeMaxDynamicSharedMemorySize, shmem);
    cudaFuncSetAttribute(moe_gemm<1>, cudaFuncAttributeMaxDynamicSharedMemorySize, shmem);

    dim3 gup(W_DIM / 128, T_TOK / 128, E_NUM);   // (8, 32, 8)
    moe_gemm<0><<<gup, 256, shmem>>>(out);
    dim3 gdn(D_DIM / 128, T_TOK / 128, E_NUM);   // (8, 32, 8)
    moe_gemm<1><<<gdn, 256, shmem>>>(out);
}

// round 6
// speedup vs baseline: 1.0509x; 1.0509x over previous
#include <cuda_runtime.h>
#include <cuda_bf16.h>
#include <math.h>
#include <stdint.h>

// ---------------- problem constants ----------------------------------------
#define T_TOK 4096
#define D_DIM 1024
#define E_NUM 8
#define W_DIM 1024
#define SLOTS 8192          // T*2 (top-2)
#define K2    2048          // stored K: [hi | lo]
#define BK    32
#define NCH   96            // effective K = 3072 (bf16x3: A=[hi|hi|lo], B=[hi|lo|hi])
#define SAS   40            // smem row stride (bf16) -> conflict-free LDSM

// ---------------- device scratch --------------------------------------------
__device__ int   g_count[E_NUM];
__device__ int   g_fill [E_NUM];
__device__ int   g_off  [E_NUM + 1];
__device__ int   g_sel  [T_TOK * 2];
__device__ float g_selw [T_TOK * 2];
__device__ int   g_tok  [SLOTS];
__device__ float g_wt   [SLOTS];
__device__ __nv_bfloat16 g_xcat [(size_t)T_TOK * K2];          // 16.8 MB
__device__ __nv_bfloat16 g_w1cat[(size_t)E_NUM * W_DIM * K2];  // 33.5 MB [e][n][k]
__device__ __nv_bfloat16 g_w2cat[(size_t)E_NUM * D_DIM * K2];  // 33.5 MB [e][d][k]
__device__ __nv_bfloat16 g_acat [(size_t)SLOTS * K2];          // 33.5 MB [slot][k]

// ---------------- PTX helpers ------------------------------------------------
__device__ __forceinline__ uint32_t smem_u32(const void* p) {
    uint32_t a;
    asm("{ .reg .u64 t; cvta.to.shared.u64 t, %1; cvt.u32.u64 %0, t; }" : "=r"(a) : "l"(p));
    return a;
}
__device__ __forceinline__ void ldsm_x4(uint32_t* r, uint32_t addr) {
    asm volatile("ldmatrix.sync.aligned.m8n8.x4.shared.b16 {%0,%1,%2,%3}, [%4];"
        : "=r"(r[0]), "=r"(r[1]), "=r"(r[2]), "=r"(r[3]) : "r"(addr));
}
__device__ __forceinline__ void mma16816(float* d, const uint32_t* a, uint32_t b0, uint32_t b1) {
    asm volatile(
        "mma.sync.aligned.m16n8k16.row.col.f32.bf16.bf16.f32 "
        "{%0,%1,%2,%3}, {%4,%5,%6,%7}, {%8,%9}, {%0,%1,%2,%3};"
        : "+f"(d[0]), "+f"(d[1]), "+f"(d[2]), "+f"(d[3])
        : "r"(a[0]), "r"(a[1]), "r"(a[2]), "r"(a[3]), "r"(b0), "r"(b1));
}

// chunk -> stored-K elem offset.  A pattern [hi|hi|lo], B pattern [hi|lo|hi]
__device__ __forceinline__ int kbA(int c) {
    return (c < 32) ? c * 32 : (c < 64 ? (c - 32) * 32 : c * 32 - 1024);
}
__device__ __forceinline__ int kbB(int c) {
    return (c < 64) ? c * 32 : (c - 64) * 32;
}

// ---------------- small kernels ---------------------------------------------
__global__ void zero_kernel(float* __restrict__ out) {
    int i = blockIdx.x * blockDim.x + threadIdx.x;
    if (i < T_TOK * D_DIM) out[i] = 0.0f;
    if (i < E_NUM) { g_count[i] = 0; g_fill[i] = 0; }
}

__global__ void router_kernel(const float* __restrict__ x, const float* __restrict__ rw) {
    int warp = (blockIdx.x * blockDim.x + threadIdx.x) >> 5;
    int lane = threadIdx.x & 31;
    if (warp >= T_TOK) return;
    const float* xr = x + (size_t)warp * D_DIM;
    float p[E_NUM];
#pragma unroll
    for (int e = 0; e < E_NUM; e++) p[e] = 0.0f;
    for (int d = lane; d < D_DIM; d += 32) {
        float xv = xr[d];
#pragma unroll
        for (int e = 0; e < E_NUM; e++) p[e] += xv * rw[e * D_DIM + d];
    }
#pragma unroll
    for (int e = 0; e < E_NUM; e++)
#pragma unroll
        for (int o = 16; o; o >>= 1) p[e] += __shfl_xor_sync(0xffffffffu, p[e], o);
    if (lane == 0) {
        int i1 = 0; float v1 = p[0];
#pragma unroll
        for (int e = 1; e < E_NUM; e++) if (p[e] > v1) { v1 = p[e]; i1 = e; }
        int i2 = -1; float v2 = -3.0e38f;
#pragma unroll
        for (int e = 0; e < E_NUM; e++) if (e != i1 && p[e] > v2) { v2 = p[e]; i2 = e; }
        float p1 = 1.0f / (1.0f + expf(-v1));
        float p2 = 1.0f / (1.0f + expf(-v2));
        float s = p1 + p2 + 1e-20f;
        g_sel [warp * 2 + 0] = i1;  g_sel [warp * 2 + 1] = i2;
        g_selw[warp * 2 + 0] = p1 / s;
        g_selw[warp * 2 + 1] = p2 / s;
        atomicAdd(&g_count[i1], 1);
        atomicAdd(&g_count[i2], 1);
    }
}

__global__ void offsets_kernel() {
    if (threadIdx.x == 0 && blockIdx.x == 0) {
        int s = 0;
#pragma unroll
        for (int e = 0; e < E_NUM; e++) { g_off[e] = s; s += g_count[e]; }
        g_off[E_NUM] = s;
    }
}

__global__ void fill_kernel() {
    int t = blockIdx.x * blockDim.x + threadIdx.x;
    if (t >= T_TOK) return;
#pragma unroll
    for (int k = 0; k < 2; k++) {
        int e = g_sel[t * 2 + k];
        int pos = g_off[e] + atomicAdd(&g_fill[e], 1);
        g_tok[pos] = t;
        g_wt [pos] = g_selw[t * 2 + k];
    }
}

// x -> [hi | lo] bf16, row-major [T][2048]
__global__ void convert_x(const float* __restrict__ x) {
    int i = blockIdx.x * blockDim.x + threadIdx.x;
    if (i >= T_TOK * D_DIM) return;
    int t = i >> 10, d = i & 1023;
    float v = x[i];
    __nv_bfloat16 hi = __float2bfloat16(v);
    __nv_bfloat16 lo = __float2bfloat16(v - __bfloat162float(hi));
    size_t b = (size_t)t * K2;
    g_xcat[b + d] = hi; g_xcat[b + 1024 + d] = lo;
}

// Per-expert 1024x1024 transpose + split -> [e][n][hi(1024)|lo(1024)]
__global__ void convert_w(const float* __restrict__ src, int sel) {
    __shared__ float tile[32][33];
    int e = blockIdx.z;
    int r0 = blockIdx.y * 32, c0 = blockIdx.x * 32;
    int src_ld  = sel ? 1024 : 8192;
    int row_off = sel ? e * 1024 : 0;
    int col_off = sel ? 0 : e * 1024;
    const float* s = src + (size_t)(row_off + r0) * src_ld + col_off + c0;
#pragma unroll
    for (int i = threadIdx.y; i < 32; i += 8)
        tile[i][threadIdx.x] = s[(size_t)i * src_ld + threadIdx.x];
    __syncthreads();
    __nv_bfloat16* d = (sel ? g_w2cat : g_w1cat) + (size_t)e * 1024 * K2;
#pragma unroll
    for (int i = threadIdx.y; i < 32; i += 8) {
        int c = c0 + i;               // dst row (N index)
        int r = r0 + threadIdx.x;     // dst col (K index)
        float v = tile[threadIdx.x][i];
        __nv_bfloat16 hi = __float2bfloat16(v);
        __nv_bfloat16 lo = __float2bfloat16(v - __bfloat162float(hi));
        size_t bi = (size_t)c * K2 + r;
        d[bi] = hi; d[bi + 1024] = lo;
    }
}

// ---------------- grouped GEMM (HMMA, reg-prefetch 2-stage, ldmatrix) -------
// MODE 0: up-proj  (A = g_xcat by token, B = g_w1cat, epi -> g_acat split)
// MODE 1: down-proj(A = g_acat by slot,  B = g_w2cat, epi -> atomicAdd out)
template <int MODE>
__global__ void __launch_bounds__(256) moe_gemm(float* __restrict__ out) {
    __shared__ __nv_bfloat16 As[2][128][SAS];
    __shared__ __nv_bfloat16 Bs[2][128][SAS];
    __shared__ int   tok_s[128];
    __shared__ float wt_s [128];

    int e = blockIdx.z;
    int cnt = g_count[e];
    int m0 = blockIdx.y * 128;
    if (m0 >= cnt) return;
    int base = g_off[e];
    int n0 = blockIdx.x * 128;

    int tid = threadIdx.x, lane = tid & 31, wid = tid >> 5;
    int wm = wid & 1, wn = wid >> 1;        // warps 2x4 -> 64x32 tile per warp
    int g = lane >> 2, tig = lane & 3;

    if (tid < 128) {
        int slot = base + m0 + tid; if (slot >= SLOTS) slot = SLOTS - 1;
        tok_s[tid] = g_tok[slot];
        wt_s [tid] = g_wt[slot];
    }
    __syncthreads();

    const __nv_bfloat16* Bexp = (MODE ? g_w2cat : g_w1cat) + (size_t)e * 1024 * K2;

    // global load assignment: 512 uint4 per tile, 2 per thread (rows r, r+64)
    int arow0 = tid >> 2, arow1 = arow0 + 64;
    int aseg  = (tid & 3) * 8;
    const __nv_bfloat16 *Ab0, *Ab1;
    if (MODE == 0) {
        Ab0 = g_xcat + (size_t)tok_s[arow0] * K2 + aseg;
        Ab1 = g_xcat + (size_t)tok_s[arow1] * K2 + aseg;
    } else {
        int s0 = base + m0 + arow0; if (s0 >= SLOTS) s0 = SLOTS - 1;
        int s1 = base + m0 + arow1; if (s1 >= SLOTS) s1 = SLOTS - 1;
        Ab0 = g_acat + (size_t)s0 * K2 + aseg;
        Ab1 = g_acat + (size_t)s1 * K2 + aseg;
    }
    const __nv_bfloat16* Bb0 = Bexp + (size_t)(n0 + arow0) * K2 + aseg;
    const __nv_bfloat16* Bb1 = Bexp + (size_t)(n0 + arow1) * K2 + aseg;

    float acc[4][4][4];
#pragma unroll
    for (int i = 0; i < 4; i++)
#pragma unroll
        for (int j = 0; j < 4; j++)
#pragma unroll
            for (int q = 0; q < 4; q++) acc[i][j][q] = 0.0f;

    // ldmatrix per-thread row/col offsets
    uint32_t ro = (lane & 7) + ((lane >> 3) & 1) * 8;   // row within 16-row tile
    uint32_t co = ((lane >> 4) & 1) * 8;                // k-half select
    uint32_t AsU = smem_u32(&As[0][0][0]);
    uint32_t BsU = smem_u32(&Bs[0][0][0]);

    // prologue: chunk 0 -> stage 0
    {
        uint4 a0 = *(const uint4*)(Ab0);
        uint4 a1 = *(const uint4*)(Ab1);
        uint4 b0 = *(const uint4*)(Bb0);
        uint4 b1 = *(const uint4*)(Bb1);
        *(uint4*)&As[0][arow0][aseg] = a0;
        *(uint4*)&As[0][arow1][aseg] = a1;
        *(uint4*)&Bs[0][arow0][aseg] = b0;
        *(uint4*)&Bs[0][arow1][aseg] = b1;
    }
    __syncthreads();

    uint4 pa0, pa1, pb0, pb1;
#pragma unroll 1
    for (int c = 0; c < NCH; c++) {
        int s = c & 1;
        bool pf = (c + 1 < NCH);
        if (pf) {
            int ka = kbA(c + 1), kb = kbB(c + 1);
            pa0 = *(const uint4*)(Ab0 + ka);
            pa1 = *(const uint4*)(Ab1 + ka);
            pb0 = *(const uint4*)(Bb0 + kb);
            pb1 = *(const uint4*)(Bb1 + kb);
        }
        uint32_t Ac = AsU + s * (128 * SAS * 2);
        uint32_t Bc = BsU + s * (128 * SAS * 2);
#pragma unroll
        for (int ks = 0; ks < 2; ks++) {
            uint32_t kc = ks * 16 + co;
            uint32_t af[4][4], bfr[2][4];
#pragma unroll
            for (int mt = 0; mt < 4; mt++)
                ldsm_x4(af[mt], Ac + (wm * 64 + mt * 16 + ro) * (SAS * 2) + kc * 2);
#pragma unroll
            for (int p = 0; p < 2; p++)
                ldsm_x4(bfr[p], Bc + (wn * 32 + p * 16 + ro) * (SAS * 2) + kc * 2);
#pragma unroll
            for (int mt = 0; mt < 4; mt++)
#pragma unroll
                for (int nt = 0; nt < 4; nt++)
                    mma16816(acc[mt][nt], af[mt], bfr[nt >> 1][nt & 1], bfr[nt >> 1][(nt & 1) + 2]);
        }
        if (pf) {
            int d = s ^ 1;
            *(uint4*)&As[d][arow0][aseg] = pa0;
            *(uint4*)&As[d][arow1][aseg] = pa1;
            *(uint4*)&Bs[d][arow0][aseg] = pb0;
            *(uint4*)&Bs[d][arow1][aseg] = pb1;
        }
        __syncthreads();
    }

    // ---------------- epilogue ----------------
#pragma unroll
    for (int mt = 0; mt < 4; mt++) {
#pragma unroll
        for (int half = 0; half < 2; half++) {
            int ml = wm * 64 + mt * 16 + g + half * 8;   // local row 0..127
            int m = m0 + ml;
            if (m >= cnt) continue;
            if (MODE == 0) {
                int slot = base + m;
                float wt = wt_s[ml];
                __nv_bfloat16* dst = g_acat + (size_t)slot * K2;
#pragma unroll
                for (int nt = 0; nt < 4; nt++) {
                    int n = n0 + wn * 32 + nt * 8 + tig * 2;
                    float h0 = acc[mt][nt][half * 2 + 0];
                    float h1 = acc[mt][nt][half * 2 + 1];
                    float a0 = (h0 > 0.0f) ? wt * h0 * h0 : 0.0f;
                    float a1 = (h1 > 0.0f) ? wt * h1 * h1 : 0.0f;
                    __nv_bfloat16 hi0 = __float2bfloat16(a0);
                    __nv_bfloat16 hi1 = __float2bfloat16(a1);
                    __nv_bfloat16 lo0 = __float2bfloat16(a0 - __bfloat162float(hi0));
                    __nv_bfloat16 lo1 = __float2bfloat16(a1 - __bfloat162float(hi1));
                    __nv_bfloat162 hh; hh.x = hi0; hh.y = hi1;
                    __nv_bfloat162 ll; ll.x = lo0; ll.y = lo1;
                    *(__nv_bfloat162*)(dst + n)        = hh;
                    *(__nv_bfloat162*)(dst + 1024 + n) = ll;
                }
            } else {
                int tok = tok_s[ml];
                float* orow = out + (size_t)tok * D_DIM;
#pragma unroll
                for (int nt = 0; nt < 4; nt++) {
                    int n = n0 + wn * 32 + nt * 8 + tig * 2;
                    atomicAdd(&orow[n],     acc[mt][nt][half * 2 + 0]);
                    atomicAdd(&orow[n + 1], acc[mt][nt][half * 2 + 1]);
                }
            }
        }
    }
}

// ---------------- launch ------------------------------------------------------
extern "C" void kernel_launch(void* const* d_in, const int* in_sizes, int n_in,
                              void* d_out, int out_size) {
    const float* x  = (const float*)d_in[0];   // [2,2048,1024]
    const float* rw = (const float*)d_in[1];   // [8,1024]
    const float* w1 = (const float*)d_in[2];   // [1024, 8192]
    const float* w2 = (const float*)d_in[3];   // [8192, 1024]
    float* out = (float*)d_out;

    zero_kernel<<<(T_TOK * D_DIM + 255) / 256, 256>>>(out);
    convert_x<<<(T_TOK * D_DIM + 255) / 256, 256>>>(x);

    dim3 tg(32, 32, E_NUM), tb(32, 8);
    convert_w<<<tg, tb>>>(w1, 0);
    convert_w<<<tg, tb>>>(w2, 1);

    router_kernel<<<(T_TOK * 32 + 255) / 256, 256>>>(x, rw);
    offsets_kernel<<<1, 32>>>();
    fill_kernel<<<(T_TOK + 255) / 256, 256>>>();

    dim3 gup(W_DIM / 128, T_TOK / 128, E_NUM);   // (8, 32, 8)
    moe_gemm<0><<<gup, 256>>>(out);
    dim3 gdn(D_DIM / 128, T_TOK / 128, E_NUM);   // (8, 32, 8)
    moe_gemm<1><<<gdn, 256>>>(out);
}